// round 4
// baseline (speedup 1.0000x reference)
#include <cuda_runtime.h>
#include <math.h>

#define BB 4
#define CC 64
#define HH 96
#define WW 320
#define HP 97   // conv rows 0..96 (row 96 = top kernel row on x[95])

// Scratch (static device globals: allowed; no runtime allocation)
__device__ float g_conv[BB*CC*HP*WW];   // ~31.8 MB
__device__ float g_mid [BB*CC*HH*WW];   // ~31.5 MB
__device__ float g_T   [BB*CC*16*WW];   // ~5.2 MB  (top-row conv at 16 special rows)

// rows f_d-1, f_d for f = {1,12,22,33,44,54,65,76}
__constant__ int c_R16[16] = {0,1, 11,12, 21,22, 32,33, 43,44, 53,54, 64,65, 75,76};

// ---------------------------------------------------------------------------
// 3x3 SAME conv, zero-extended input, output rows 0..96 into g_conv.
// Block: 64 co x (8 rows x 32 cols) tile, 256 threads, each 8co x 8px.
// grid = (WW/32=10, ceil(HP/8)=13, BB)
// ---------------------------------------------------------------------------
__global__ __launch_bounds__(256, 2)
void conv3_kernel(const float* __restrict__ in_ext, const float* __restrict__ wk)
{
    const float* in = in_ext ? in_ext : g_mid;
    __shared__ __align__(16) float Xs[10][34];
    __shared__ __align__(16) float Ws[9][64];

    const int x0  = blockIdx.x * 32;
    const int y0  = blockIdx.y * 8;
    const int b   = blockIdx.z;
    const int tid = threadIdx.x;
    const int cog  = tid >> 5;          // 0..7 : co group (8 co each)
    const int pg   = tid & 31;
    const int row  = pg >> 2;           // 0..7 : tile row
    const int colg = (pg & 3) * 8;      // 0,8,16,24 : col group (8 cols)

    float acc[8][8];
    #pragma unroll
    for (int i = 0; i < 8; i++)
        #pragma unroll
        for (int j = 0; j < 8; j++) acc[i][j] = 0.f;

    for (int ci = 0; ci < CC; ci++) {
        const float* xin = in + (size_t)(b*CC + ci) * HH * WW;
        // input tile with halo (zero-padded)
        for (int idx = tid; idx < 340; idx += 256) {
            int r = idx / 34, c = idx - r * 34;
            int gy = y0 - 1 + r;
            int gx = x0 - 1 + c;
            float v = 0.f;
            if (gy >= 0 && gy < HH && gx >= 0 && gx < WW) v = xin[gy*WW + gx];
            Xs[r][c] = v;
        }
        // weights for this ci: Ws[k][co]
        for (int idx = tid; idx < 576; idx += 256) {
            int co = idx / 9, k = idx - co * 9;
            Ws[k][co] = wk[(co*CC + ci)*9 + k];
        }
        __syncthreads();

        #pragma unroll
        for (int ky = 0; ky < 3; ky++) {
            float xv[10];
            #pragma unroll
            for (int m = 0; m < 10; m++) xv[m] = Xs[row + ky][colg + m];
            #pragma unroll
            for (int kx = 0; kx < 3; kx++) {
                const float4* wp = reinterpret_cast<const float4*>(&Ws[ky*3 + kx][0]) + cog*2;
                float4 wa = wp[0], wb = wp[1];
                float wv[8] = {wa.x, wa.y, wa.z, wa.w, wb.x, wb.y, wb.z, wb.w};
                #pragma unroll
                for (int i = 0; i < 8; i++)
                    #pragma unroll
                    for (int j = 0; j < 8; j++)
                        acc[i][j] = fmaf(wv[i], xv[j + kx], acc[i][j]);
            }
        }
        __syncthreads();
    }

    const int y = y0 + row;
    if (y < HP) {
        #pragma unroll
        for (int i = 0; i < 8; i++) {
            int co = cog*8 + i;
            float* op = g_conv + ((size_t)(b*CC + co) * HP + y) * WW + x0 + colg;
            float4 v0 = make_float4(acc[i][0], acc[i][1], acc[i][2], acc[i][3]);
            float4 v1 = make_float4(acc[i][4], acc[i][5], acc[i][6], acc[i][7]);
            reinterpret_cast<float4*>(op)[0] = v0;
            reinterpret_cast<float4*>(op)[1] = v1;
        }
    }
}

// ---------------------------------------------------------------------------
// Top-kernel-row conv T[r] = sum_{ci,kx} W[co,ci,0,kx] * x[ci, r, x+kx-1]
// at the 16 rows in c_R16. grid = (10, 4 row-groups, BB), 256 threads.
// Thread: 8 co x 4 rows x 1 col.
// ---------------------------------------------------------------------------
__global__ __launch_bounds__(256)
void trow_kernel(const float* __restrict__ in_ext, const float* __restrict__ wk)
{
    const float* in = in_ext ? in_ext : g_mid;
    __shared__ __align__(16) float Xs4[4][34];
    __shared__ __align__(16) float Ws3[3][64];

    const int x0  = blockIdx.x * 32;
    const int rg  = blockIdx.y;         // 0..3 -> rows c_R16[4*rg .. 4*rg+3]
    const int b   = blockIdx.z;
    const int tid = threadIdx.x;
    const int cog = tid >> 5;           // 0..7
    const int lx  = tid & 31;

    float acc[8][4];
    #pragma unroll
    for (int i = 0; i < 8; i++)
        #pragma unroll
        for (int r = 0; r < 4; r++) acc[i][r] = 0.f;

    for (int ci = 0; ci < CC; ci++) {
        for (int idx = tid; idx < 136; idx += 256) {
            int r = idx / 34, c = idx - r * 34;
            int gy = c_R16[rg*4 + r];           // always in [0,96)
            int gx = x0 - 1 + c;
            float v = 0.f;
            if (gx >= 0 && gx < WW) v = in[((size_t)(b*CC + ci) * HH + gy) * WW + gx];
            Xs4[r][c] = v;
        }
        for (int idx = tid; idx < 192; idx += 256) {
            int co = idx / 3, kx = idx - co * 3;
            Ws3[kx][co] = wk[(co*CC + ci)*9 + kx];   // ky = 0 row
        }
        __syncthreads();

        #pragma unroll
        for (int rr = 0; rr < 4; rr++) {
            float xv[3] = { Xs4[rr][lx], Xs4[rr][lx + 1], Xs4[rr][lx + 2] };
            #pragma unroll
            for (int kx = 0; kx < 3; kx++) {
                const float4* wp = reinterpret_cast<const float4*>(&Ws3[kx][0]) + cog*2;
                float4 wa = wp[0], wb = wp[1];
                float wv[8] = {wa.x, wa.y, wa.z, wa.w, wb.x, wb.y, wb.z, wb.w};
                #pragma unroll
                for (int i = 0; i < 8; i++)
                    acc[i][rr] = fmaf(wv[i], xv[kx], acc[i][rr]);
            }
        }
        __syncthreads();
    }

    #pragma unroll
    for (int i = 0; i < 8; i++) {
        int co = cog*8 + i;
        #pragma unroll
        for (int rr = 0; rr < 4; rr++)
            g_T[((size_t)(b*CC + co) * 16 + rg*4 + rr) * WW + x0 + lx] = acc[i][rr];
    }
}

// ---------------------------------------------------------------------------
// Plane-blend + max + bias + relu.
// out[y] = relu(bias + max_d [(1-w_d)*Cz[y+f_d] + w_d*Cz[y+f_d+1]])  (rows>96 -> 0)
// y==0 subtracts the top-pad correction using g_T.
// grid = (WW/32=10, BB*CC), 256 threads. Shared: full 97-row column strip.
// ---------------------------------------------------------------------------
__global__ __launch_bounds__(256)
void blend_kernel(const float* __restrict__ bias, float* __restrict__ out_ext)
{
    float* out = out_ext ? out_ext : g_mid;
    __shared__ float s[HP][32];

    const int x0  = blockIdx.x * 32;
    const int bc  = blockIdx.y;                 // b*CC + c
    const int tid = threadIdx.x;
    const float* src = g_conv + (size_t)bc * HP * WW + x0;

    for (int idx = tid; idx < HP*32; idx += 256) {
        int r = idx >> 5, c = idx & 31;
        s[r][c] = src[(size_t)r * WW + c];
    }
    __syncthreads();

    const int fi[8]   = {1, 12, 22, 33, 44, 54, 65, 76};
    const float wf[8] = {0.52f, 0.16f, 0.80f, 0.44f, 0.08f, 0.72f, 0.36f, 0.0f};

    const int lx = tid & 31;
    const int ty = tid >> 5;                    // 0..7, each handles 12 rows
    const float bv = bias[bc & (CC - 1)];

    for (int yy = 0; yy < 12; yy++) {
        int y = ty * 12 + yy;
        float m = -3.0e38f;
        #pragma unroll
        for (int d = 0; d < 8; d++) {
            int r0 = y + fi[d];
            float v0 = (r0 <= HH) ? s[r0][lx]     : 0.f;   // row <= 96
            float v1 = (r0 <  HH) ? s[r0 + 1][lx] : 0.f;   // row+1 <= 96
            float v  = (1.f - wf[d]) * v0 + wf[d] * v1;
            m = fmaxf(m, v);
        }
        if (y == 0) {
            // exact top-boundary correction: subtract K_top applied to warpedz[-1]
            m = -3.0e38f;
            #pragma unroll
            for (int d = 0; d < 8; d++) {
                float T0 = g_T[((size_t)bc * 16 + 2*d    ) * WW + x0 + lx];
                float T1 = g_T[((size_t)bc * 16 + 2*d + 1) * WW + x0 + lx];
                float v0 = s[fi[d]][lx]     - T0;
                float v1 = s[fi[d] + 1][lx] - T1;
                float v  = (1.f - wf[d]) * v0 + wf[d] * v1;
                m = fmaxf(m, v);
            }
        }
        out[((size_t)bc * HH + y) * WW + x0 + lx] = fmaxf(m + bv, 0.f);
    }
}

// ---------------------------------------------------------------------------
extern "C" void kernel_launch(void* const* d_in, const int* in_sizes, int n_in,
                              void* d_out, int out_size)
{
    const float* x  = (const float*)d_in[0];
    const float* W1 = (const float*)d_in[1];
    const float* b1 = (const float*)d_in[2];
    const float* W2 = (const float*)d_in[3];
    const float* b2 = (const float*)d_in[4];
    float* out = (float*)d_out;

    dim3 gc(WW/32, (HP + 7) / 8, BB);   // 10 x 13 x 4
    dim3 gt(WW/32, 4, BB);              // 10 x 4  x 4
    dim3 gb(WW/32, BB*CC);              // 10 x 256

    // Layer 1
    conv3_kernel<<<gc, 256>>>(x, W1);
    trow_kernel <<<gt, 256>>>(x, W1);
    blend_kernel<<<gb, 256>>>(b1, nullptr);   // -> g_mid (includes relu)
    // Layer 2
    conv3_kernel<<<gc, 256>>>(nullptr, W2);   // in = g_mid
    trow_kernel <<<gt, 256>>>(nullptr, W2);
    blend_kernel<<<gb, 256>>>(b2, out);
}